// round 10
// baseline (speedup 1.0000x reference)
#include <cuda_runtime.h>
#include <cuda_bf16.h>

// ---------------------------------------------------------------------------
// SpMiddleFHDLite — sparse block1 + padded dense convs, packed fma.rn.f32x2
// with kw-axis packing: (v_kw0,v_kw1) loaded as one u64 feeds one FFMA2
// against (w_kw0,w_kw1); kw2 paired across outputs. Epilogue sums halves.
// ---------------------------------------------------------------------------

#define EPS 1e-3f
typedef unsigned long long u64;

static constexpr int B_ = 2;

static constexpr int PD1 = 23, PH1 = 258, PW1 = 258;   // h1 + halo(1,1,1)
static constexpr long long PLANE1 = (long long)PD1 * PH1 * PW1;
static constexpr int PD2 = 11, PH2 = 130, PW2 = 130;   // h2 + halo(0,1,1)
static constexpr long long PLANE2 = (long long)PD2 * PH2 * PW2;
static constexpr long long PLANE3 = 5LL * 64 * 64;     // h3 (no halo)

__device__ __align__(256) float         g_h1[B_ * 16 * PLANE1];
__device__ __align__(256) unsigned char g_m1[B_ * PLANE1 + 16];
__device__ __align__(256) float         g_h2[B_ * 32 * PLANE2];
__device__ __align__(256) unsigned char g_m2[B_ * PLANE2 + 16];
__device__ __align__(256) float         g_h3[B_ * 64 * PLANE3];
__device__ __align__(256) unsigned char g_m3[B_ * PLANE3 + 16];

// ---------------------------------------------------------------------------
__device__ __forceinline__ u64 pk2(float lo, float hi) {
    u64 r;
    unsigned l = __float_as_uint(lo), h = __float_as_uint(hi);
    asm("mov.b64 %0, {%1,%2};" : "=l"(r) : "r"(l), "r"(h));
    return r;
}
__device__ __forceinline__ void upk2(u64 v, float& lo, float& hi) {
    unsigned l, h;
    asm("mov.b64 {%0,%1}, %2;" : "=r"(l), "=r"(h) : "l"(v));
    lo = __uint_as_float(l); hi = __uint_as_float(h);
}
__device__ __forceinline__ void fma2(u64& d, u64 a, u64 b) {
    asm("fma.rn.f32x2 %0, %1, %2, %0;" : "+l"(d) : "l"(a), "l"(b));
}

// ---------------------------------------------------------------------------
// Sparse block1: each thread = (voxel, co). Scatter w.f into h1 accumulator.
// ---------------------------------------------------------------------------
__global__ void __launch_bounds__(256)
scatter_conv1(const float* __restrict__ vf, const int* __restrict__ coors,
              float* __restrict__ h1, unsigned char* __restrict__ m1,
              const float* __restrict__ W, int nv) {
    __shared__ float sw[16 * 3 * 27];
    int tid = threadIdx.x;
    for (int i = tid; i < 16 * 3 * 27; i += 256) sw[i] = W[i];
    __syncthreads();

    int g = blockIdx.x * 256 + tid;
    int vi = g >> 4, co = g & 15;
    if (vi >= nv) return;

    float f0 = vf[3 * vi], f1 = vf[3 * vi + 1], f2 = vf[3 * vi + 2];
    int4 cz = *reinterpret_cast<const int4*>(coors + 4 * vi);
    int b = cz.x, z = cz.y, y = cz.z, x = cz.w;

    int odl[2], kdl[2], nz = 1;
    if (z & 1) { odl[0] = (z - 1) >> 1; kdl[0] = 2; odl[1] = (z + 1) >> 1; kdl[1] = 0;
                 nz = (((z + 1) >> 1) < 21) ? 2 : 1; }
    else       { odl[0] = z >> 1; kdl[0] = 1; }
    int ohl[2], khl[2], ny = 1;
    if (y & 1) { ohl[0] = (y - 1) >> 1; khl[0] = 2; ohl[1] = (y + 1) >> 1; khl[1] = 0;
                 ny = (((y + 1) >> 1) < 256) ? 2 : 1; }
    else       { ohl[0] = y >> 1; khl[0] = 1; }
    int owl[2], kwl[2], nx = 1;
    if (x & 1) { owl[0] = (x - 1) >> 1; kwl[0] = 2; owl[1] = (x + 1) >> 1; kwl[1] = 0;
                 nx = (((x + 1) >> 1) < 256) ? 2 : 1; }
    else       { owl[0] = x >> 1; kwl[0] = 1; }

    const float* wc = &sw[co * 81];
    float* hc = h1 + (size_t)(b * 16 + co) * PLANE1;
    unsigned char* mb = m1 + (size_t)b * PLANE1;

    for (int iz = 0; iz < nz; iz++)
        for (int iy = 0; iy < ny; iy++)
            for (int ix = 0; ix < nx; ix++) {
                int k = (kdl[iz] * 3 + khl[iy]) * 3 + kwl[ix];
                float val = wc[k] * f0 + wc[27 + k] * f1 + wc[54 + k] * f2;
                size_t sp = (size_t)(odl[iz] + 1) * (PH1 * PW1)
                          + (size_t)(ohl[iy] + 1) * PW1 + (owl[ix] + 1);
                atomicAdd(hc + sp, val);
                if (co == 0) mb[sp] = 1;
            }
}

// ---------------------------------------------------------------------------
// BN+ReLU+mask elementwise pass, in place.
// ---------------------------------------------------------------------------
template<int CH, long long PLANE>
__global__ void __launch_bounds__(256)
bn_pass(float* __restrict__ h, const unsigned char* __restrict__ m,
        const float* __restrict__ Ga, const float* __restrict__ Be,
        const float* __restrict__ Rm, const float* __restrict__ Rv) {
    int c = blockIdx.y % CH;
    int b = blockIdx.y / CH;
    float inv = Ga[c] * rsqrtf(Rv[c] + EPS);
    float sh  = Be[c] - Rm[c] * inv;
    size_t p = ((size_t)blockIdx.x * 256 + threadIdx.x) * 4;
    if (p >= (size_t)PLANE) return;
    float4* vp = reinterpret_cast<float4*>(h + (size_t)blockIdx.y * PLANE + p);
    float4 v = *vp;
    uchar4 mm = *reinterpret_cast<const uchar4*>(m + (size_t)b * PLANE + p);
    v.x = mm.x ? fmaxf(fmaf(v.x, inv, sh), 0.f) : 0.f;
    v.y = mm.y ? fmaxf(fmaf(v.y, inv, sh), 0.f) : 0.f;
    v.z = mm.z ? fmaxf(fmaf(v.z, inv, sh), 0.f) : 0.f;
    v.w = mm.w ? fmaxf(fmaf(v.w, inv, sh), 0.f) : 0.f;
    *vp = v;
}

// ---------------------------------------------------------------------------
// Padded dense conv, packed f32x2 FMA.
// KW==3 && SW==2 path ("kw-packed"): input u64 load (v_kw0,v_kw1) feeds one
// FFMA2 vs weight pair (w_kw0,w_kw1) per output; kw2 taps paired across
// outputs. smem weights per (cil,kd,kh,co): {(w0,w1),(w2,w2)} as ulonglong2.
// Generic path (conv4, KW==1): output-paired as before; old weight layout.
// NSPLIT>1: raw partial sums via atomicAdd (bn applied by later bn_pass).
// ---------------------------------------------------------------------------
template<int CI, int CO, int COG, int TW, int TH, int BY, int NSPLIT,
         int IDP, int IHP, int IWP,
         int OD, int OH, int OW,
         int OPD, int OPH, int OPW,
         int KD, int KH, int KW, int SD, int SH, int SW>
__global__ void __launch_bounds__(32 * BY)
conv_pad(const float* __restrict__ in, const unsigned char* __restrict__ mi,
         float* __restrict__ out, unsigned char* __restrict__ mo,
         const float* __restrict__ Wt, const float* __restrict__ Ga,
         const float* __restrict__ Be, const float* __restrict__ Rm,
         const float* __restrict__ Rv) {
    constexpr int NCOG = CO / COG;
    constexpr int NT = TW * TH;      // even
    constexpr int NP = NT / 2;
    constexpr int NTHR = 32 * BY;
    constexpr int CIL = CI / NSPLIT;
    constexpr int ODP = OD + 2 * OPD, OHP = OH + 2 * OPH, OWP = OW + 2 * OPW;
    constexpr bool KW3S2 = (KW == 3 && SW == 2);
    static_assert(COG % 2 == 0, "COG even");
    extern __shared__ u64 sw2[];

    const int tid = threadIdx.y * 32 + threadIdx.x;
    int zi = blockIdx.z;
    const int cg = zi % NCOG; zi /= NCOG;
    const int od = zi % OD;  zi /= OD;
    const int b  = zi % B_;
    const int sp = zi / B_;          // ci split index
    const int ci0 = sp * CIL;

    // ---- stage weights ----
    if (KW3S2) {
        constexpr int WGROUPS = CIL * KD * KH;
        for (int i = tid; i < WGROUPS * COG; i += NTHR) {
            int co = i % COG; int r = i / COG;
            int kh = r % KH; r /= KH;
            int kd = r % KD; int cil = r / KD;
            const float* wb =
                &Wt[((((cg * COG + co) * CI + ci0 + cil) * KD + kd) * KH + kh) * 3];
            float w0 = wb[0], w1 = wb[1], w2 = wb[2];
            sw2[2 * i + 0] = pk2(w0, w1);
            sw2[2 * i + 1] = pk2(w2, w2);
        }
    } else {
        constexpr int WSTEPS = CIL * KD * KH * KW;
        for (int i = tid; i < WSTEPS * COG; i += NTHR) {
            int co = i % COG; int r = i / COG;
            int kw = r % KW; r /= KW;
            int kh = r % KH; r /= KH;
            int kd = r % KD; int cil = r / KD;
            float w = Wt[((((cg * COG + co) * CI + ci0 + cil) * KD + kd) * KH + kh) * KW + kw];
            sw2[i] = pk2(w, w);
        }
    }
    __syncthreads();

    const int ow0 = threadIdx.x;                           // + 32*tw
    const int oh0 = (blockIdx.y * BY + threadIdx.y) * TH;  // + th

    unsigned any[NT];
#pragma unroll
    for (int t = 0; t < NT; t++) any[t] = 0;
    if (NSPLIT == 1 || (cg == 0 && sp == 0)) {
        const unsigned char* mb = mi + (size_t)b * IDP * IHP * IWP;
#pragma unroll
        for (int kd = 0; kd < KD; kd++)
#pragma unroll
            for (int kh = 0; kh < KH; kh++)
#pragma unroll
                for (int th = 0; th < TH; th++) {
                    const unsigned char* mrow =
                        mb + ((size_t)(od * SD + kd) * IHP + (oh0 + th) * SH + kh) * IWP;
#pragma unroll
                    for (int kw = 0; kw < KW; kw++)
#pragma unroll
                        for (int tw = 0; tw < TW; tw++)
                            any[th * TW + tw] |= mrow[(ow0 + 32 * tw) * SW + kw];
                }
    }

    // accumulators
    u64 accA[KW3S2 ? COG : 1][KW3S2 ? NT : 1];   // (kw0,kw1) halves per output
    u64 accB[KW3S2 ? COG : 1][KW3S2 ? NP : 1];   // kw2, outputs paired
    u64 accG[KW3S2 ? 1 : COG][KW3S2 ? 1 : NP];   // generic path
#pragma unroll
    for (int co = 0; co < (KW3S2 ? COG : 1); co++) {
#pragma unroll
        for (int t = 0; t < (KW3S2 ? NT : 1); t++) accA[co][t] = 0ull;
#pragma unroll
        for (int p = 0; p < (KW3S2 ? NP : 1); p++) accB[co][p] = 0ull;
    }
#pragma unroll
    for (int co = 0; co < (KW3S2 ? 1 : COG); co++)
#pragma unroll
        for (int p = 0; p < (KW3S2 ? 1 : NP); p++) accG[co][p] = 0ull;

    const float* inb = in + ((size_t)b * CI + ci0) * IDP * IHP * IWP;
#pragma unroll 1
    for (int cil = 0; cil < CIL; cil++) {
#pragma unroll
        for (int kd = 0; kd < KD; kd++) {
            const float* pl = inb + ((size_t)cil * IDP + od * SD + kd) * (IHP * IWP);
#pragma unroll
            for (int kh = 0; kh < KH; kh++) {
                const float* row[TH];
#pragma unroll
                for (int th = 0; th < TH; th++)
                    row[th] = pl + ((size_t)(oh0 + th) * SH + kh) * IWP;

                if (KW3S2) {
                    // taps: (v0,v1) as one u64 load; v2 scalar
                    u64 v01[NT]; float v2[NT];
#pragma unroll
                    for (int th = 0; th < TH; th++)
#pragma unroll
                        for (int tw = 0; tw < TW; tw++) {
                            int iw = (ow0 + 32 * tw) * 2;
                            v01[th * TW + tw] =
                                *reinterpret_cast<const u64*>(row[th] + iw);
                            v2[th * TW + tw] = row[th][iw + 2];
                        }
                    u64 v2p[NP];
#pragma unroll
                    for (int p = 0; p < NP; p++)
                        v2p[p] = pk2(v2[2 * p], v2[2 * p + 1]);

                    const u64* wp = &sw2[((cil * KD + kd) * KH + kh) * COG * 2];
#pragma unroll
                    for (int co = 0; co < COG; co++) {
                        ulonglong2 ww =
                            *reinterpret_cast<const ulonglong2*>(wp + 2 * co);
#pragma unroll
                        for (int t = 0; t < NT; t++) fma2(accA[co][t], v01[t], ww.x);
#pragma unroll
                        for (int p = 0; p < NP; p++) fma2(accB[co][p], v2p[p], ww.y);
                    }
                } else {
#pragma unroll
                    for (int kw = 0; kw < KW; kw++) {
                        u64 vp[NP];
#pragma unroll
                        for (int p = 0; p < NP; p++) {
                            int t0 = 2 * p, t1 = 2 * p + 1;
                            int th0 = t0 / TW, tw0 = t0 % TW;
                            int th1 = t1 / TW, tw1 = t1 % TW;
                            float v0 = row[th0][(ow0 + 32 * tw0) * SW + kw];
                            float v1 = row[th1][(ow0 + 32 * tw1) * SW + kw];
                            vp[p] = pk2(v0, v1);
                        }
                        const u64* wp = &sw2[(((cil * KD + kd) * KH + kh) * KW + kw) * COG];
#pragma unroll
                        for (int co2 = 0; co2 < COG / 2; co2++) {
                            ulonglong2 ww =
                                *reinterpret_cast<const ulonglong2*>(wp + 2 * co2);
#pragma unroll
                            for (int p = 0; p < NP; p++) fma2(accG[2 * co2][p], vp[p], ww.x);
#pragma unroll
                            for (int p = 0; p < NP; p++) fma2(accG[2 * co2 + 1][p], vp[p], ww.y);
                        }
                    }
                }
            }
        }
    }

    // reduce to per-output sums
    float sums[COG][NT];
    if (KW3S2) {
#pragma unroll
        for (int co = 0; co < COG; co++)
#pragma unroll
            for (int p = 0; p < NP; p++) {
                float b0, b1;
                upk2(accB[co][p], b0, b1);
                float a0lo, a0hi, a1lo, a1hi;
                upk2(accA[co][2 * p], a0lo, a0hi);
                upk2(accA[co][2 * p + 1], a1lo, a1hi);
                sums[co][2 * p]     = a0lo + a0hi + b0;
                sums[co][2 * p + 1] = a1lo + a1hi + b1;
            }
    } else {
#pragma unroll
        for (int co = 0; co < COG; co++)
#pragma unroll
            for (int p = 0; p < NP; p++) {
                float a0, a1;
                upk2(accG[co][p], a0, a1);
                sums[co][2 * p] = a0;
                sums[co][2 * p + 1] = a1;
            }
    }

    if (NSPLIT > 1) {
#pragma unroll
        for (int co = 0; co < COG; co++) {
            int c = cg * COG + co;
            size_t obc = ((size_t)(b * CO + c) * ODP + od) * ((size_t)OHP * OWP);
#pragma unroll
            for (int t = 0; t < NT; t++) {
                int th = t / TW, tw = t % TW;
                atomicAdd(&out[obc + (size_t)(oh0 + th) * OWP + (ow0 + 32 * tw)],
                          sums[co][t]);
            }
        }
        if (cg == 0 && sp == 0) {
            size_t mbc = ((size_t)b * ODP + od) * ((size_t)OHP * OWP);
#pragma unroll
            for (int t = 0; t < NT; t++) {
                int th = t / TW, tw = t % TW;
                mo[mbc + (size_t)(oh0 + th) * OWP + (ow0 + 32 * tw)] = any[t] ? 1 : 0;
            }
        }
    } else {
#pragma unroll
        for (int co = 0; co < COG; co++) {
            int c = cg * COG + co;
            float inv = Ga[c] * rsqrtf(Rv[c] + EPS);
            float sh  = Be[c] - Rm[c] * inv;
            size_t obc = ((size_t)(b * CO + c) * ODP + od + OPD) * ((size_t)OHP * OWP);
#pragma unroll
            for (int t = 0; t < NT; t++) {
                int th = t / TW, tw = t % TW;
                float v = any[t] ? fmaxf(fmaf(sums[co][t], inv, sh), 0.f) : 0.f;
                out[obc + (size_t)(oh0 + th + OPH) * OWP + (ow0 + 32 * tw + OPW)] = v;
            }
        }
        if (cg == 0) {
            size_t mbc = ((size_t)b * ODP + od + OPD) * ((size_t)OHP * OWP);
#pragma unroll
            for (int t = 0; t < NT; t++) {
                int th = t / TW, tw = t % TW;
                mo[mbc + (size_t)(oh0 + th + OPH) * OWP + (ow0 + 32 * tw + OPW)] = any[t] ? 1 : 0;
            }
        }
    }
}

// ---------------------------------------------------------------------------
extern "C" void kernel_launch(void* const* d_in, const int* in_sizes, int n_in,
                              void* d_out, int out_size) {
    const float* vf    = (const float*)d_in[0];
    const int*   coors = (const int*)d_in[1];
    const float *w1 = (const float*)d_in[3],  *gg1 = (const float*)d_in[4],
                *b1 = (const float*)d_in[5],  *rm1 = (const float*)d_in[6],
                *rv1 = (const float*)d_in[7];
    const float *w2 = (const float*)d_in[8],  *gg2 = (const float*)d_in[9],
                *b2 = (const float*)d_in[10], *rm2 = (const float*)d_in[11],
                *rv2 = (const float*)d_in[12];
    const float *w3 = (const float*)d_in[13], *gg3 = (const float*)d_in[14],
                *b3 = (const float*)d_in[15], *rm3 = (const float*)d_in[16],
                *rv3 = (const float*)d_in[17];
    const float *w4 = (const float*)d_in[18], *gg4 = (const float*)d_in[19],
                *b4 = (const float*)d_in[20], *rm4 = (const float*)d_in[21],
                *rv4 = (const float*)d_in[22];
    float* out = (float*)d_out;
    const int nv = in_sizes[0] / 3;

    float *h1, *h2, *h3;
    unsigned char *m1, *m2, *m3;
    cudaGetSymbolAddress((void**)&h1, g_h1);
    cudaGetSymbolAddress((void**)&m1, g_m1);
    cudaGetSymbolAddress((void**)&h2, g_h2);
    cudaGetSymbolAddress((void**)&m2, g_m2);
    cudaGetSymbolAddress((void**)&h3, g_h3);
    cudaGetSymbolAddress((void**)&m3, g_m3);

    cudaMemsetAsync(h1, 0, (size_t)B_ * 16 * PLANE1 * sizeof(float));
    cudaMemsetAsync(m1, 0, (size_t)B_ * PLANE1 + 16);
    cudaMemsetAsync(h2, 0, (size_t)B_ * 32 * PLANE2 * sizeof(float));
    cudaMemsetAsync(m2, 0, (size_t)B_ * PLANE2 + 16);
    cudaMemsetAsync(h3, 0, (size_t)B_ * 64 * PLANE3 * sizeof(float));

    // block1 sparse
    {
        int nthreads = nv * 16;
        scatter_conv1<<<(nthreads + 255) / 256, 256>>>(vf, coors, h1, m1, w1, nv);
        dim3 grid((unsigned)((PLANE1 / 4 + 255) / 256), B_ * 16);
        bn_pass<16, PLANE1><<<grid, 256>>>(h1, m1, gg1, b1, rm1, rv1);
    }

    dim3 blk(32, 4, 1);   // 128-thread blocks

    // block2: 16->32, (23,258,258)pad -> (11,128,128), out halo (0,1,1)
    // COG=4, TW=4, TH=1, BY=4. grid: y=32, z=8*11*2=176 -> 5632 blocks
    {
        auto k = conv_pad<16, 32, 4, 4, 1, 4, 1, 23, 258, 258, 11, 128, 128,
                          0, 1, 1, 3, 3, 3, 2, 2, 2>;
        size_t smem = (16ull * 9) * 4 * 2 * 8;  // 9216
        dim3 grid(1, 32, B_ * 11 * 8);
        k<<<grid, blk, smem>>>(h1, m1, h2, m2, w2, gg2, b2, rm2, rv2);
    }
    // block3: 32->64, (11,130,130)pad -> (5,64,64) raw, CI split x2
    // COG=4, TW=2, TH=2, BY=4. grid: y=8, z=16*5*2*2=320 -> 2560 blocks
    {
        auto k = conv_pad<32, 64, 4, 2, 2, 4, 2, 11, 130, 130, 5, 64, 64,
                          0, 0, 0, 3, 3, 3, 2, 2, 2>;
        size_t smem = (16ull * 9) * 4 * 2 * 8;  // 9216 (CIL=16)
        dim3 grid(1, 8, 16 * 5 * B_ * 2);
        k<<<grid, blk, smem>>>(h2, m2, h3, m3, w3, gg3, b3, rm3, rv3);
        dim3 bgrid((unsigned)((PLANE3 / 4 + 255) / 256), B_ * 64);
        bn_pass<64, PLANE3><<<bgrid, 256>>>(h3, m3, gg3, b3, rm3, rv3);
    }
    // block4: 64->64, k(3,1,1) s(2,1,1), (5,64,64) -> (2,64,64) = d_out
    // generic path. COG=8, TW=2, TH=2, BY=4. grid: y=8 covers oh 0..63
    {
        auto k = conv_pad<64, 64, 8, 2, 2, 4, 1, 5, 64, 64, 2, 64, 64,
                          0, 0, 0, 3, 1, 1, 2, 1, 1>;
        size_t smem = (64ull * 3) * 8 * 8;   // 12288
        dim3 grid(1, 8, 8 * 2 * B_);
        k<<<grid, blk, smem>>>(h3, m3, out, m3, w4, gg4, b4, rm4, rv4);
    }
}

// round 12
// speedup vs baseline: 1.0637x; 1.0637x over previous
#include <cuda_runtime.h>
#include <cuda_bf16.h>

// ---------------------------------------------------------------------------
// SpMiddleFHDLite — sparse block1 + padded dense convs (R9 inner loop),
// CI-split to shrink smem, 8 blocks/SM via launch_bounds, split raw output
// buffers + bn_sum epilogue pass (no atomics).
// ---------------------------------------------------------------------------

#define EPS 1e-3f
typedef unsigned long long u64;

static constexpr int B_ = 2;

static constexpr int PD1 = 23, PH1 = 258, PW1 = 258;   // h1 + halo(1,1,1)
static constexpr long long PLANE1 = (long long)PD1 * PH1 * PW1;
static constexpr int PD2 = 11, PH2 = 130, PW2 = 130;   // h2 + halo(0,1,1)
static constexpr long long PLANE2 = (long long)PD2 * PH2 * PW2;
static constexpr long long PLANE3 = 5LL * 64 * 64;     // h3 (no halo)

__device__ __align__(256) float         g_h1[B_ * 16 * PLANE1];
__device__ __align__(256) unsigned char g_m1[B_ * PLANE1 + 16];
__device__ __align__(256) float         g_h2[B_ * 32 * PLANE2];
__device__ __align__(256) unsigned char g_m2[B_ * PLANE2 + 16];
__device__ __align__(256) float         g_h3[B_ * 64 * PLANE3];
__device__ __align__(256) unsigned char g_m3[B_ * PLANE3 + 16];
// raw split accumulators (interior fully overwritten each call; halos masked)
__device__ __align__(256) float         g_h2raw[2ull * B_ * 32 * PLANE2];
__device__ __align__(256) float         g_h3raw[4ull * B_ * 64 * PLANE3];

// ---------------------------------------------------------------------------
__device__ __forceinline__ u64 pk2(float lo, float hi) {
    u64 r;
    unsigned l = __float_as_uint(lo), h = __float_as_uint(hi);
    asm("mov.b64 %0, {%1,%2};" : "=l"(r) : "r"(l), "r"(h));
    return r;
}
__device__ __forceinline__ void upk2(u64 v, float& lo, float& hi) {
    unsigned l, h;
    asm("mov.b64 {%0,%1}, %2;" : "=r"(l), "=r"(h) : "l"(v));
    lo = __uint_as_float(l); hi = __uint_as_float(h);
}
__device__ __forceinline__ void fma2(u64& d, u64 a, u64 b) {
    asm("fma.rn.f32x2 %0, %1, %2, %0;" : "+l"(d) : "l"(a), "l"(b));
}

// ---------------------------------------------------------------------------
// Sparse block1: each thread = (voxel, co). Scatter w.f into h1 accumulator.
// ---------------------------------------------------------------------------
__global__ void __launch_bounds__(256)
scatter_conv1(const float* __restrict__ vf, const int* __restrict__ coors,
              float* __restrict__ h1, unsigned char* __restrict__ m1,
              const float* __restrict__ W, int nv) {
    __shared__ float sw[16 * 3 * 27];
    int tid = threadIdx.x;
    for (int i = tid; i < 16 * 3 * 27; i += 256) sw[i] = W[i];
    __syncthreads();

    int g = blockIdx.x * 256 + tid;
    int vi = g >> 4, co = g & 15;
    if (vi >= nv) return;

    float f0 = vf[3 * vi], f1 = vf[3 * vi + 1], f2 = vf[3 * vi + 2];
    int4 cz = *reinterpret_cast<const int4*>(coors + 4 * vi);
    int b = cz.x, z = cz.y, y = cz.z, x = cz.w;

    int odl[2], kdl[2], nz = 1;
    if (z & 1) { odl[0] = (z - 1) >> 1; kdl[0] = 2; odl[1] = (z + 1) >> 1; kdl[1] = 0;
                 nz = (((z + 1) >> 1) < 21) ? 2 : 1; }
    else       { odl[0] = z >> 1; kdl[0] = 1; }
    int ohl[2], khl[2], ny = 1;
    if (y & 1) { ohl[0] = (y - 1) >> 1; khl[0] = 2; ohl[1] = (y + 1) >> 1; khl[1] = 0;
                 ny = (((y + 1) >> 1) < 256) ? 2 : 1; }
    else       { ohl[0] = y >> 1; khl[0] = 1; }
    int owl[2], kwl[2], nx = 1;
    if (x & 1) { owl[0] = (x - 1) >> 1; kwl[0] = 2; owl[1] = (x + 1) >> 1; kwl[1] = 0;
                 nx = (((x + 1) >> 1) < 256) ? 2 : 1; }
    else       { owl[0] = x >> 1; kwl[0] = 1; }

    const float* wc = &sw[co * 81];
    float* hc = h1 + (size_t)(b * 16 + co) * PLANE1;
    unsigned char* mb = m1 + (size_t)b * PLANE1;

    for (int iz = 0; iz < nz; iz++)
        for (int iy = 0; iy < ny; iy++)
            for (int ix = 0; ix < nx; ix++) {
                int k = (kdl[iz] * 3 + khl[iy]) * 3 + kwl[ix];
                float val = wc[k] * f0 + wc[27 + k] * f1 + wc[54 + k] * f2;
                size_t sp = (size_t)(odl[iz] + 1) * (PH1 * PW1)
                          + (size_t)(ohl[iy] + 1) * PW1 + (owl[ix] + 1);
                atomicAdd(hc + sp, val);
                if (co == 0) mb[sp] = 1;
            }
}

// ---------------------------------------------------------------------------
// BN+ReLU+mask elementwise pass, in place (block1 epilogue).
// ---------------------------------------------------------------------------
template<int CH, long long PLANE>
__global__ void __launch_bounds__(256)
bn_pass(float* __restrict__ h, const unsigned char* __restrict__ m,
        const float* __restrict__ Ga, const float* __restrict__ Be,
        const float* __restrict__ Rm, const float* __restrict__ Rv) {
    int c = blockIdx.y % CH;
    int b = blockIdx.y / CH;
    float inv = Ga[c] * rsqrtf(Rv[c] + EPS);
    float sh  = Be[c] - Rm[c] * inv;
    size_t p = ((size_t)blockIdx.x * 256 + threadIdx.x) * 4;
    if (p >= (size_t)PLANE) return;
    float4* vp = reinterpret_cast<float4*>(h + (size_t)blockIdx.y * PLANE + p);
    float4 v = *vp;
    uchar4 mm = *reinterpret_cast<const uchar4*>(m + (size_t)b * PLANE + p);
    v.x = mm.x ? fmaxf(fmaf(v.x, inv, sh), 0.f) : 0.f;
    v.y = mm.y ? fmaxf(fmaf(v.y, inv, sh), 0.f) : 0.f;
    v.z = mm.z ? fmaxf(fmaf(v.z, inv, sh), 0.f) : 0.f;
    v.w = mm.w ? fmaxf(fmaf(v.w, inv, sh), 0.f) : 0.f;
    *vp = v;
}

// ---------------------------------------------------------------------------
// Sum NS split raw buffers + BN + ReLU + mask -> dst.
// raw layout: [split][b][c][plane], split stride = B_*CH*PLANE.
// ---------------------------------------------------------------------------
template<int CH, long long PLANE, int NS>
__global__ void __launch_bounds__(256)
bn_sum(float* __restrict__ dst, const float* __restrict__ raw,
       const unsigned char* __restrict__ m,
       const float* __restrict__ Ga, const float* __restrict__ Be,
       const float* __restrict__ Rm, const float* __restrict__ Rv) {
    int c = blockIdx.y % CH;
    int b = blockIdx.y / CH;
    float inv = Ga[c] * rsqrtf(Rv[c] + EPS);
    float sh  = Be[c] - Rm[c] * inv;
    size_t p = ((size_t)blockIdx.x * 256 + threadIdx.x) * 4;
    if (p >= (size_t)PLANE) return;
    size_t base = (size_t)blockIdx.y * PLANE + p;
    constexpr size_t SSTR = (size_t)B_ * CH * PLANE;
    float4 s = *reinterpret_cast<const float4*>(raw + base);
#pragma unroll
    for (int k = 1; k < NS; k++) {
        float4 t = *reinterpret_cast<const float4*>(raw + k * SSTR + base);
        s.x += t.x; s.y += t.y; s.z += t.z; s.w += t.w;
    }
    uchar4 mm = *reinterpret_cast<const uchar4*>(m + (size_t)b * PLANE + p);
    float4 v;
    v.x = mm.x ? fmaxf(fmaf(s.x, inv, sh), 0.f) : 0.f;
    v.y = mm.y ? fmaxf(fmaf(s.y, inv, sh), 0.f) : 0.f;
    v.z = mm.z ? fmaxf(fmaf(s.z, inv, sh), 0.f) : 0.f;
    v.w = mm.w ? fmaxf(fmaf(s.w, inv, sh), 0.f) : 0.f;
    *reinterpret_cast<float4*>(dst + base) = v;
}

// ---------------------------------------------------------------------------
// Padded dense conv, packed f32x2 FMA (R9 inner loop).
// Thread tile: TW x TH outputs x COG channels; ow0 = blockIdx.x*32*TW + lane.
// NSPLIT>1: plain stores of raw partial sums into per-split buffer
// (out + sp*B_*CO*ODP*OHP*OWP); bn_sum applies BN later. No atomics.
// KW==3 && SW==2: kw0/kw1 taps share one float2 load.
// ---------------------------------------------------------------------------
template<int CI, int CO, int COG, int TW, int TH, int BY, int NSPLIT,
         int IDP, int IHP, int IWP,
         int OD, int OH, int OW,
         int OPD, int OPH, int OPW,
         int KD, int KH, int KW, int SD, int SH, int SW>
__global__ void __launch_bounds__(32 * BY, 8)
conv_pad(const float* __restrict__ in, const unsigned char* __restrict__ mi,
         float* __restrict__ out, unsigned char* __restrict__ mo,
         const float* __restrict__ Wt, const float* __restrict__ Ga,
         const float* __restrict__ Be, const float* __restrict__ Rm,
         const float* __restrict__ Rv) {
    constexpr int NCOG = CO / COG;
    constexpr int NT = TW * TH;      // even
    constexpr int NP = NT / 2;
    constexpr int NTHR = 32 * BY;
    constexpr int CIL = CI / NSPLIT;
    constexpr int WSTEPS = CIL * KD * KH * KW;
    constexpr int ODP = OD + 2 * OPD, OHP = OH + 2 * OPH, OWP = OW + 2 * OPW;
    constexpr bool KW3S2 = (KW == 3 && SW == 2);
    static_assert(COG % 2 == 0, "COG even");
    extern __shared__ u64 sw2[];

    const int tid = threadIdx.y * 32 + threadIdx.x;
    int zi = blockIdx.z;
    const int cg = zi % NCOG; zi /= NCOG;
    const int od = zi % OD;  zi /= OD;
    const int b  = zi % B_;
    const int sp = zi / B_;          // ci split index
    const int ci0 = sp * CIL;

    for (int i = tid; i < WSTEPS * COG; i += NTHR) {
        int co = i % COG; int r = i / COG;
        int kw = r % KW; r /= KW;
        int kh = r % KH; r /= KH;
        int kd = r % KD; int cil = r / KD;
        float w = Wt[((((cg * COG + co) * CI + ci0 + cil) * KD + kd) * KH + kh) * KW + kw];
        sw2[i] = pk2(w, w);
    }
    __syncthreads();

    const int ow0 = blockIdx.x * (32 * TW) + threadIdx.x;  // + 32*tw
    const int oh0 = (blockIdx.y * BY + threadIdx.y) * TH;  // + th

    unsigned any[NT];
#pragma unroll
    for (int t = 0; t < NT; t++) any[t] = 0;
    if (NSPLIT == 1 || (cg == 0 && sp == 0)) {
        const unsigned char* mb = mi + (size_t)b * IDP * IHP * IWP;
#pragma unroll
        for (int kd = 0; kd < KD; kd++)
#pragma unroll
            for (int kh = 0; kh < KH; kh++)
#pragma unroll
                for (int th = 0; th < TH; th++) {
                    const unsigned char* mrow =
                        mb + ((size_t)(od * SD + kd) * IHP + (oh0 + th) * SH + kh) * IWP;
#pragma unroll
                    for (int kw = 0; kw < KW; kw++)
#pragma unroll
                        for (int tw = 0; tw < TW; tw++)
                            any[th * TW + tw] |= mrow[(ow0 + 32 * tw) * SW + kw];
                }
    }

    u64 acc[COG][NP];
#pragma unroll
    for (int co = 0; co < COG; co++)
#pragma unroll
        for (int p = 0; p < NP; p++) acc[co][p] = 0ull;

    const float* inb = in + ((size_t)b * CI + ci0) * IDP * IHP * IWP;
#pragma unroll 1
    for (int cil = 0; cil < CIL; cil++) {
#pragma unroll
        for (int kd = 0; kd < KD; kd++) {
            const float* pl = inb + ((size_t)cil * IDP + od * SD + kd) * (IHP * IWP);
#pragma unroll
            for (int kh = 0; kh < KH; kh++) {
                const float* row[TH];
#pragma unroll
                for (int th = 0; th < TH; th++)
                    row[th] = pl + ((size_t)(oh0 + th) * SH + kh) * IWP;

                if (KW3S2) {
                    float2 a01[NT]; float a2[NT];
#pragma unroll
                    for (int th = 0; th < TH; th++)
#pragma unroll
                        for (int tw = 0; tw < TW; tw++) {
                            int iw = (ow0 + 32 * tw) * 2;
                            a01[th * TW + tw] =
                                *reinterpret_cast<const float2*>(row[th] + iw);
                            a2[th * TW + tw] = row[th][iw + 2];
                        }
#pragma unroll
                    for (int kw = 0; kw < 3; kw++) {
                        u64 vp[NP];
#pragma unroll
                        for (int p = 0; p < NP; p++) {
                            int t0 = 2 * p, t1 = 2 * p + 1;
                            float v0 = (kw == 0) ? a01[t0].x : (kw == 1) ? a01[t0].y : a2[t0];
                            float v1 = (kw == 0) ? a01[t1].x : (kw == 1) ? a01[t1].y : a2[t1];
                            vp[p] = pk2(v0, v1);
                        }
                        const u64* wp = &sw2[(((cil * KD + kd) * KH + kh) * 3 + kw) * COG];
#pragma unroll
                        for (int co2 = 0; co2 < COG / 2; co2++) {
                            ulonglong2 ww =
                                *reinterpret_cast<const ulonglong2*>(wp + 2 * co2);
#pragma unroll
                            for (int p = 0; p < NP; p++) fma2(acc[2 * co2][p], vp[p], ww.x);
#pragma unroll
                            for (int p = 0; p < NP; p++) fma2(acc[2 * co2 + 1][p], vp[p], ww.y);
                        }
                    }
                } else {
#pragma unroll
                    for (int kw = 0; kw < KW; kw++) {
                        u64 vp[NP];
#pragma unroll
                        for (int p = 0; p < NP; p++) {
                            int t0 = 2 * p, t1 = 2 * p + 1;
                            int th0 = t0 / TW, tw0 = t0 % TW;
                            int th1 = t1 / TW, tw1 = t1 % TW;
                            float v0 = row[th0][(ow0 + 32 * tw0) * SW + kw];
                            float v1 = row[th1][(ow0 + 32 * tw1) * SW + kw];
                            vp[p] = pk2(v0, v1);
                        }
                        const u64* wp = &sw2[(((cil * KD + kd) * KH + kh) * KW + kw) * COG];
#pragma unroll
                        for (int co2 = 0; co2 < COG / 2; co2++) {
                            ulonglong2 ww =
                                *reinterpret_cast<const ulonglong2*>(wp + 2 * co2);
#pragma unroll
                            for (int p = 0; p < NP; p++) fma2(acc[2 * co2][p], vp[p], ww.x);
#pragma unroll
                            for (int p = 0; p < NP; p++) fma2(acc[2 * co2 + 1][p], vp[p], ww.y);
                        }
                    }
                }
            }
        }
    }

    if (NSPLIT > 1) {
        // plain stores of raw partial sums into this split's buffer
        const size_t soff = (size_t)sp * B_ * CO * ODP * ((size_t)OHP * OWP);
#pragma unroll
        for (int co = 0; co < COG; co++) {
            int c = cg * COG + co;
            size_t obc = soff + ((size_t)(b * CO + c) * ODP + od + OPD) * ((size_t)OHP * OWP);
#pragma unroll
            for (int p = 0; p < NP; p++) {
                float a0, a1;
                upk2(acc[co][p], a0, a1);
                int t0 = 2 * p, t1 = 2 * p + 1;
                int th0 = t0 / TW, tw0 = t0 % TW;
                int th1 = t1 / TW, tw1 = t1 % TW;
                out[obc + (size_t)(oh0 + th0 + OPH) * OWP + (ow0 + 32 * tw0 + OPW)] = a0;
                out[obc + (size_t)(oh0 + th1 + OPH) * OWP + (ow0 + 32 * tw1 + OPW)] = a1;
            }
        }
        if (cg == 0 && sp == 0) {
            size_t mbc = ((size_t)b * ODP + od + OPD) * ((size_t)OHP * OWP);
#pragma unroll
            for (int t = 0; t < NT; t++) {
                int th = t / TW, tw = t % TW;
                mo[mbc + (size_t)(oh0 + th + OPH) * OWP + (ow0 + 32 * tw + OPW)] = any[t] ? 1 : 0;
            }
        }
    } else {
#pragma unroll
        for (int co = 0; co < COG; co++) {
            int c = cg * COG + co;
            float inv = Ga[c] * rsqrtf(Rv[c] + EPS);
            float sh  = Be[c] - Rm[c] * inv;
            size_t obc = ((size_t)(b * CO + c) * ODP + od + OPD) * ((size_t)OHP * OWP);
#pragma unroll
            for (int p = 0; p < NP; p++) {
                float a0, a1;
                upk2(acc[co][p], a0, a1);
                int t0 = 2 * p, t1 = 2 * p + 1;
                int th0 = t0 / TW, tw0 = t0 % TW;
                int th1 = t1 / TW, tw1 = t1 % TW;
                float v0 = any[t0] ? fmaxf(fmaf(a0, inv, sh), 0.f) : 0.f;
                float v1 = any[t1] ? fmaxf(fmaf(a1, inv, sh), 0.f) : 0.f;
                out[obc + (size_t)(oh0 + th0 + OPH) * OWP + (ow0 + 32 * tw0 + OPW)] = v0;
                out[obc + (size_t)(oh0 + th1 + OPH) * OWP + (ow0 + 32 * tw1 + OPW)] = v1;
            }
        }
        if (cg == 0) {
            size_t mbc = ((size_t)b * ODP + od + OPD) * ((size_t)OHP * OWP);
#pragma unroll
            for (int t = 0; t < NT; t++) {
                int th = t / TW, tw = t % TW;
                mo[mbc + (size_t)(oh0 + th + OPH) * OWP + (ow0 + 32 * tw + OPW)] = any[t] ? 1 : 0;
            }
        }
    }
}

// ---------------------------------------------------------------------------
extern "C" void kernel_launch(void* const* d_in, const int* in_sizes, int n_in,
                              void* d_out, int out_size) {
    const float* vf    = (const float*)d_in[0];
    const int*   coors = (const int*)d_in[1];
    const float *w1 = (const float*)d_in[3],  *gg1 = (const float*)d_in[4],
                *b1 = (const float*)d_in[5],  *rm1 = (const float*)d_in[6],
                *rv1 = (const float*)d_in[7];
    const float *w2 = (const float*)d_in[8],  *gg2 = (const float*)d_in[9],
                *b2 = (const float*)d_in[10], *rm2 = (const float*)d_in[11],
                *rv2 = (const float*)d_in[12];
    const float *w3 = (const float*)d_in[13], *gg3 = (const float*)d_in[14],
                *b3 = (const float*)d_in[15], *rm3 = (const float*)d_in[16],
                *rv3 = (const float*)d_in[17];
    const float *w4 = (const float*)d_in[18], *gg4 = (const float*)d_in[19],
                *b4 = (const float*)d_in[20], *rm4 = (const float*)d_in[21],
                *rv4 = (const float*)d_in[22];
    float* out = (float*)d_out;
    const int nv = in_sizes[0] / 3;

    float *h1, *h2, *h3, *h2r, *h3r;
    unsigned char *m1, *m2, *m3;
    cudaGetSymbolAddress((void**)&h1, g_h1);
    cudaGetSymbolAddress((void**)&m1, g_m1);
    cudaGetSymbolAddress((void**)&h2, g_h2);
    cudaGetSymbolAddress((void**)&m2, g_m2);
    cudaGetSymbolAddress((void**)&h3, g_h3);
    cudaGetSymbolAddress((void**)&m3, g_m3);
    cudaGetSymbolAddress((void**)&h2r, g_h2raw);
    cudaGetSymbolAddress((void**)&h3r, g_h3raw);

    cudaMemsetAsync(h1, 0, (size_t)B_ * 16 * PLANE1 * sizeof(float));
    cudaMemsetAsync(m1, 0, (size_t)B_ * PLANE1 + 16);
    cudaMemsetAsync(m2, 0, (size_t)B_ * PLANE2 + 16);   // h2 halo mask = 0

    // block1 sparse: scatter-conv then BN pass
    {
        int nthreads = nv * 16;
        scatter_conv1<<<(nthreads + 255) / 256, 256>>>(vf, coors, h1, m1, w1, nv);
        dim3 grid((unsigned)((PLANE1 / 4 + 255) / 256), B_ * 16);
        bn_pass<16, PLANE1><<<grid, 256>>>(h1, m1, gg1, b1, rm1, rv1);
    }

    dim3 blk(32, 4, 1);   // 128-thread blocks

    // block2: 16->32, (23,258,258)pad -> raw splits -> bn_sum -> h2 (halo 0,1,1)
    // COG=8, TW=2, TH=2, BY=4, NSPLIT=2 (CIL=8, smem 13824)
    // grid: x=2, y=16, z=4*11*2*2=176 -> 5632 blocks
    {
        auto k = conv_pad<16, 32, 8, 2, 2, 4, 2, 23, 258, 258, 11, 128, 128,
                          0, 1, 1, 3, 3, 3, 2, 2, 2>;
        size_t smem = (8ull * 27) * 8 * 8;   // 13824
        dim3 grid(2, 16, 4 * 11 * B_ * 2);
        k<<<grid, blk, smem>>>(h1, m1, h2r, m2, w2, gg2, b2, rm2, rv2);
        dim3 bgrid((unsigned)((PLANE2 / 4 + 255) / 256), B_ * 32);
        bn_sum<32, PLANE2, 2><<<bgrid, 256>>>(h2, h2r, m2, gg2, b2, rm2, rv2);
    }
    // block3: 32->64, (11,130,130)pad -> raw splits -> bn_sum -> h3
    // COG=8, TW=2, TH=2, BY=4, NSPLIT=4 (CIL=8, smem 13824)
    // grid: x=1, y=8, z=8*5*2*4=320 -> 2560 blocks
    {
        auto k = conv_pad<32, 64, 8, 2, 2, 4, 4, 11, 130, 130, 5, 64, 64,
                          0, 0, 0, 3, 3, 3, 2, 2, 2>;
        size_t smem = (8ull * 27) * 8 * 8;   // 13824
        dim3 grid(1, 8, 8 * 5 * B_ * 4);
        k<<<grid, blk, smem>>>(h2, m2, h3r, m3, w3, gg3, b3, rm3, rv3);
        dim3 bgrid((unsigned)((PLANE3 / 4 + 255) / 256), B_ * 64);
        bn_sum<64, PLANE3, 4><<<bgrid, 256>>>(h3, h3r, m3, gg3, b3, rm3, rv3);
    }
    // block4: 64->64, k(3,1,1) s(2,1,1), (5,64,64) -> (2,64,64) = d_out
    // COG=8, TW=2, TH=2, BY=4, NSPLIT=1. grid: y=8 covers oh 0..63
    {
        auto k = conv_pad<64, 64, 8, 2, 2, 4, 1, 5, 64, 64, 2, 64, 64,
                          0, 0, 0, 3, 1, 1, 2, 1, 1>;
        size_t smem = (64ull * 3) * 8 * 8;   // 12288
        dim3 grid(1, 8, 8 * 2 * B_);
        k<<<grid, blk, smem>>>(h3, m3, out, m3, w4, gg4, b4, rm4, rv4);
    }
}

// round 13
// speedup vs baseline: 1.0986x; 1.0328x over previous
#include <cuda_runtime.h>
#include <cuda_bf16.h>

// ---------------------------------------------------------------------------
// SpMiddleFHDLite — sparse block1 + padded dense convs, packed fma.rn.f32x2.
// R9 shape (COG=8, NP=2, float2 kw-overlap loads, LDS.128 paired weights,
// 128-thread blocks). R13: conv3 NSPLIT=8 to kill wave-quantization tail.
// ---------------------------------------------------------------------------

#define EPS 1e-3f
typedef unsigned long long u64;

static constexpr int B_ = 2;

// h1 padded for block2's pad (1,1,1): (23,258,258)
static constexpr int PD1 = 23, PH1 = 258, PW1 = 258;
static constexpr long long PLANE1 = (long long)PD1 * PH1 * PW1;
// h2 padded for block3's pad (0,1,1): (11,130,130)
static constexpr int PD2 = 11, PH2 = 130, PW2 = 130;
static constexpr long long PLANE2 = (long long)PD2 * PH2 * PW2;
static constexpr long long PLANE3 = 5LL * 64 * 64;   // h3 (no halo)

__device__ __align__(256) float         g_h1[B_ * 16 * PLANE1];
__device__ __align__(256) unsigned char g_m1[B_ * PLANE1 + 16];
__device__ __align__(256) float         g_h2[B_ * 32 * PLANE2];
__device__ __align__(256) unsigned char g_m2[B_ * PLANE2 + 16];
__device__ __align__(256) float         g_h3[B_ * 64 * PLANE3];
__device__ __align__(256) unsigned char g_m3[B_ * PLANE3 + 16];

// ---------------------------------------------------------------------------
__device__ __forceinline__ u64 pk2(float lo, float hi) {
    u64 r;
    unsigned l = __float_as_uint(lo), h = __float_as_uint(hi);
    asm("mov.b64 %0, {%1,%2};" : "=l"(r) : "r"(l), "r"(h));
    return r;
}
__device__ __forceinline__ void upk2(u64 v, float& lo, float& hi) {
    unsigned l, h;
    asm("mov.b64 {%0,%1}, %2;" : "=r"(l), "=r"(h) : "l"(v));
    lo = __uint_as_float(l); hi = __uint_as_float(h);
}
__device__ __forceinline__ void fma2(u64& d, u64 a, u64 b) {
    asm("fma.rn.f32x2 %0, %1, %2, %0;" : "+l"(d) : "l"(a), "l"(b));
}

// ---------------------------------------------------------------------------
// Sparse block1: each thread = (voxel, co). Scatter w.f into h1 accumulator.
// ---------------------------------------------------------------------------
__global__ void __launch_bounds__(256)
scatter_conv1(const float* __restrict__ vf, const int* __restrict__ coors,
              float* __restrict__ h1, unsigned char* __restrict__ m1,
              const float* __restrict__ W, int nv) {
    __shared__ float sw[16 * 3 * 27];
    int tid = threadIdx.x;
    for (int i = tid; i < 16 * 3 * 27; i += 256) sw[i] = W[i];
    __syncthreads();

    int g = blockIdx.x * 256 + tid;
    int vi = g >> 4, co = g & 15;
    if (vi >= nv) return;

    float f0 = vf[3 * vi], f1 = vf[3 * vi + 1], f2 = vf[3 * vi + 2];
    int4 cz = *reinterpret_cast<const int4*>(coors + 4 * vi);
    int b = cz.x, z = cz.y, y = cz.z, x = cz.w;

    int odl[2], kdl[2], nz = 1;
    if (z & 1) { odl[0] = (z - 1) >> 1; kdl[0] = 2; odl[1] = (z + 1) >> 1; kdl[1] = 0;
                 nz = (((z + 1) >> 1) < 21) ? 2 : 1; }
    else       { odl[0] = z >> 1; kdl[0] = 1; }
    int ohl[2], khl[2], ny = 1;
    if (y & 1) { ohl[0] = (y - 1) >> 1; khl[0] = 2; ohl[1] = (y + 1) >> 1; khl[1] = 0;
                 ny = (((y + 1) >> 1) < 256) ? 2 : 1; }
    else       { ohl[0] = y >> 1; khl[0] = 1; }
    int owl[2], kwl[2], nx = 1;
    if (x & 1) { owl[0] = (x - 1) >> 1; kwl[0] = 2; owl[1] = (x + 1) >> 1; kwl[1] = 0;
                 nx = (((x + 1) >> 1) < 256) ? 2 : 1; }
    else       { owl[0] = x >> 1; kwl[0] = 1; }

    const float* wc = &sw[co * 81];
    float* hc = h1 + (size_t)(b * 16 + co) * PLANE1;
    unsigned char* mb = m1 + (size_t)b * PLANE1;

    for (int iz = 0; iz < nz; iz++)
        for (int iy = 0; iy < ny; iy++)
            for (int ix = 0; ix < nx; ix++) {
                int k = (kdl[iz] * 3 + khl[iy]) * 3 + kwl[ix];
                float val = wc[k] * f0 + wc[27 + k] * f1 + wc[54 + k] * f2;
                size_t sp = (size_t)(odl[iz] + 1) * (PH1 * PW1)
                          + (size_t)(ohl[iy] + 1) * PW1 + (owl[ix] + 1);
                atomicAdd(hc + sp, val);
                if (co == 0) mb[sp] = 1;
            }
}

// ---------------------------------------------------------------------------
// BN+ReLU+mask elementwise pass, in place.
// ---------------------------------------------------------------------------
template<int CH, long long PLANE>
__global__ void __launch_bounds__(256)
bn_pass(float* __restrict__ h, const unsigned char* __restrict__ m,
        const float* __restrict__ Ga, const float* __restrict__ Be,
        const float* __restrict__ Rm, const float* __restrict__ Rv) {
    int c = blockIdx.y % CH;
    int b = blockIdx.y / CH;
    float inv = Ga[c] * rsqrtf(Rv[c] + EPS);
    float sh  = Be[c] - Rm[c] * inv;
    size_t p = ((size_t)blockIdx.x * 256 + threadIdx.x) * 4;
    if (p >= (size_t)PLANE) return;
    float4* vp = reinterpret_cast<float4*>(h + (size_t)blockIdx.y * PLANE + p);
    float4 v = *vp;
    uchar4 mm = *reinterpret_cast<const uchar4*>(m + (size_t)b * PLANE + p);
    v.x = mm.x ? fmaxf(fmaf(v.x, inv, sh), 0.f) : 0.f;
    v.y = mm.y ? fmaxf(fmaf(v.y, inv, sh), 0.f) : 0.f;
    v.z = mm.z ? fmaxf(fmaf(v.z, inv, sh), 0.f) : 0.f;
    v.w = mm.w ? fmaxf(fmaf(v.w, inv, sh), 0.f) : 0.f;
    *vp = v;
}

// ---------------------------------------------------------------------------
// Padded dense conv (+ optional fused BN/ReLU/mask), packed f32x2 FMA.
// Thread tile: TW x TH outputs x COG channels (COG even).
// Weights read from smem as ulonglong2 (2 co per LDS.128).
// NSPLIT>1: raw partial sums via atomicAdd (bn applied by later bn_pass).
// KW==3 && SW==2: kw0/kw1 taps share one float2 load.
// ---------------------------------------------------------------------------
template<int CI, int CO, int COG, int TW, int TH, int BY, int NSPLIT,
         int IDP, int IHP, int IWP,
         int OD, int OH, int OW,
         int OPD, int OPH, int OPW,
         int KD, int KH, int KW, int SD, int SH, int SW>
__global__ void __launch_bounds__(32 * BY)
conv_pad(const float* __restrict__ in, const unsigned char* __restrict__ mi,
         float* __restrict__ out, unsigned char* __restrict__ mo,
         const float* __restrict__ Wt, const float* __restrict__ Ga,
         const float* __restrict__ Be, const float* __restrict__ Rm,
         const float* __restrict__ Rv) {
    constexpr int NCOG = CO / COG;
    constexpr int NT = TW * TH;      // even
    constexpr int NP = NT / 2;
    constexpr int NTHR = 32 * BY;
    constexpr int CIL = CI / NSPLIT;
    constexpr int WSTEPS = CIL * KD * KH * KW;
    constexpr int ODP = OD + 2 * OPD, OHP = OH + 2 * OPH, OWP = OW + 2 * OPW;
    constexpr bool KW3S2 = (KW == 3 && SW == 2);
    static_assert(COG % 2 == 0, "COG even");
    extern __shared__ u64 sw2[];

    const int tid = threadIdx.y * 32 + threadIdx.x;
    int zi = blockIdx.z;
    const int cg = zi % NCOG; zi /= NCOG;
    const int od = zi % OD;  zi /= OD;
    const int b  = zi % B_;
    const int sp = zi / B_;          // ci split index
    const int ci0 = sp * CIL;

    for (int i = tid; i < WSTEPS * COG; i += NTHR) {
        int co = i % COG; int r = i / COG;
        int kw = r % KW; r /= KW;
        int kh = r % KH; r /= KH;
        int kd = r % KD; int cil = r / KD;
        float w = Wt[((((cg * COG + co) * CI + ci0 + cil) * KD + kd) * KH + kh) * KW + kw];
        sw2[i] = pk2(w, w);
    }
    __syncthreads();

    const int ow0 = threadIdx.x;                           // + 32*tw
    const int oh0 = (blockIdx.y * BY + threadIdx.y) * TH;  // + th

    unsigned any[NT];
#pragma unroll
    for (int t = 0; t < NT; t++) any[t] = 0;
    if (NSPLIT == 1 || (cg == 0 && sp == 0)) {
        const unsigned char* mb = mi + (size_t)b * IDP * IHP * IWP;
#pragma unroll
        for (int kd = 0; kd < KD; kd++)
#pragma unroll
            for (int kh = 0; kh < KH; kh++)
#pragma unroll
                for (int th = 0; th < TH; th++) {
                    const unsigned char* mrow =
                        mb + ((size_t)(od * SD + kd) * IHP + (oh0 + th) * SH + kh) * IWP;
#pragma unroll
                    for (int kw = 0; kw < KW; kw++)
#pragma unroll
                        for (int tw = 0; tw < TW; tw++)
                            any[th * TW + tw] |= mrow[(ow0 + 32 * tw) * SW + kw];
                }
    }

    u64 acc[COG][NP];
#pragma unroll
    for (int co = 0; co < COG; co++)
#pragma unroll
        for (int p = 0; p < NP; p++) acc[co][p] = 0ull;

    const float* inb = in + ((size_t)b * CI + ci0) * IDP * IHP * IWP;
#pragma unroll 1
    for (int cil = 0; cil < CIL; cil++) {
#pragma unroll
        for (int kd = 0; kd < KD; kd++) {
            const float* pl = inb + ((size_t)cil * IDP + od * SD + kd) * (IHP * IWP);
#pragma unroll
            for (int kh = 0; kh < KH; kh++) {
                const float* row[TH];
#pragma unroll
                for (int th = 0; th < TH; th++)
                    row[th] = pl + ((size_t)(oh0 + th) * SH + kh) * IWP;

                if (KW3S2) {
                    float2 a01[NT]; float a2[NT];
#pragma unroll
                    for (int th = 0; th < TH; th++)
#pragma unroll
                        for (int tw = 0; tw < TW; tw++) {
                            int iw = (ow0 + 32 * tw) * 2;
                            a01[th * TW + tw] =
                                *reinterpret_cast<const float2*>(row[th] + iw);
                            a2[th * TW + tw] = row[th][iw + 2];
                        }
#pragma unroll
                    for (int kw = 0; kw < 3; kw++) {
                        u64 vp[NP];
#pragma unroll
                        for (int p = 0; p < NP; p++) {
                            int t0 = 2 * p, t1 = 2 * p + 1;
                            float v0 = (kw == 0) ? a01[t0].x : (kw == 1) ? a01[t0].y : a2[t0];
                            float v1 = (kw == 0) ? a01[t1].x : (kw == 1) ? a01[t1].y : a2[t1];
                            vp[p] = pk2(v0, v1);
                        }
                        const u64* wp = &sw2[(((cil * KD + kd) * KH + kh) * 3 + kw) * COG];
#pragma unroll
                        for (int co2 = 0; co2 < COG / 2; co2++) {
                            ulonglong2 ww =
                                *reinterpret_cast<const ulonglong2*>(wp + 2 * co2);
#pragma unroll
                            for (int p = 0; p < NP; p++) fma2(acc[2 * co2][p], vp[p], ww.x);
#pragma unroll
                            for (int p = 0; p < NP; p++) fma2(acc[2 * co2 + 1][p], vp[p], ww.y);
                        }
                    }
                } else {
#pragma unroll
                    for (int kw = 0; kw < KW; kw++) {
                        u64 vp[NP];
#pragma unroll
                        for (int p = 0; p < NP; p++) {
                            int t0 = 2 * p, t1 = 2 * p + 1;
                            int th0 = t0 / TW, tw0 = t0 % TW;
                            int th1 = t1 / TW, tw1 = t1 % TW;
                            float v0 = row[th0][(ow0 + 32 * tw0) * SW + kw];
                            float v1 = row[th1][(ow0 + 32 * tw1) * SW + kw];
                            vp[p] = pk2(v0, v1);
                        }
                        const u64* wp = &sw2[(((cil * KD + kd) * KH + kh) * KW + kw) * COG];
#pragma unroll
                        for (int co2 = 0; co2 < COG / 2; co2++) {
                            ulonglong2 ww =
                                *reinterpret_cast<const ulonglong2*>(wp + 2 * co2);
#pragma unroll
                            for (int p = 0; p < NP; p++) fma2(acc[2 * co2][p], vp[p], ww.x);
#pragma unroll
                            for (int p = 0; p < NP; p++) fma2(acc[2 * co2 + 1][p], vp[p], ww.y);
                        }
                    }
                }
            }
        }
    }

    if (NSPLIT > 1) {
#pragma unroll
        for (int co = 0; co < COG; co++) {
            int c = cg * COG + co;
            size_t obc = ((size_t)(b * CO + c) * ODP + od) * ((size_t)OHP * OWP);
#pragma unroll
            for (int p = 0; p < NP; p++) {
                float a0, a1;
                upk2(acc[co][p], a0, a1);
                int t0 = 2 * p, t1 = 2 * p + 1;
                int th0 = t0 / TW, tw0 = t0 % TW;
                int th1 = t1 / TW, tw1 = t1 % TW;
                atomicAdd(&out[obc + (size_t)(oh0 + th0) * OWP + (ow0 + 32 * tw0)], a0);
                atomicAdd(&out[obc + (size_t)(oh0 + th1) * OWP + (ow0 + 32 * tw1)], a1);
            }
        }
        if (cg == 0 && sp == 0) {
            size_t mbc = ((size_t)b * ODP + od) * ((size_t)OHP * OWP);
#pragma unroll
            for (int t = 0; t < NT; t++) {
                int th = t / TW, tw = t % TW;
                mo[mbc + (size_t)(oh0 + th) * OWP + (ow0 + 32 * tw)] = any[t] ? 1 : 0;
            }
        }
    } else {
#pragma unroll
        for (int co = 0; co < COG; co++) {
            int c = cg * COG + co;
            float inv = Ga[c] * rsqrtf(Rv[c] + EPS);
            float sh  = Be[c] - Rm[c] * inv;
            size_t obc = ((size_t)(b * CO + c) * ODP + od + OPD) * ((size_t)OHP * OWP);
#pragma unroll
            for (int p = 0; p < NP; p++) {
                float a0, a1;
                upk2(acc[co][p], a0, a1);
                int t0 = 2 * p, t1 = 2 * p + 1;
                int th0 = t0 / TW, tw0 = t0 % TW;
                int th1 = t1 / TW, tw1 = t1 % TW;
                float v0 = any[t0] ? fmaxf(fmaf(a0, inv, sh), 0.f) : 0.f;
                float v1 = any[t1] ? fmaxf(fmaf(a1, inv, sh), 0.f) : 0.f;
                out[obc + (size_t)(oh0 + th0 + OPH) * OWP + (ow0 + 32 * tw0 + OPW)] = v0;
                out[obc + (size_t)(oh0 + th1 + OPH) * OWP + (ow0 + 32 * tw1 + OPW)] = v1;
            }
        }
        if (cg == 0) {
            size_t mbc = ((size_t)b * ODP + od + OPD) * ((size_t)OHP * OWP);
#pragma unroll
            for (int t = 0; t < NT; t++) {
                int th = t / TW, tw = t % TW;
                mo[mbc + (size_t)(oh0 + th + OPH) * OWP + (ow0 + 32 * tw + OPW)] = any[t] ? 1 : 0;
            }
        }
    }
}

// ---------------------------------------------------------------------------
extern "C" void kernel_launch(void* const* d_in, const int* in_sizes, int n_in,
                              void* d_out, int out_size) {
    const float* vf    = (const float*)d_in[0];
    const int*   coors = (const int*)d_in[1];
    const float *w1 = (const float*)d_in[3],  *gg1 = (const float*)d_in[4],
                *b1 = (const float*)d_in[5],  *rm1 = (const float*)d_in[6],
                *rv1 = (const float*)d_in[7];
    const float *w2 = (const float*)d_in[8],  *gg2 = (const float*)d_in[9],
                *b2 = (const float*)d_in[10], *rm2 = (const float*)d_in[11],
                *rv2 = (const float*)d_in[12];
    const float *w3 = (const float*)d_in[13], *gg3 = (const float*)d_in[14],
                *b3 = (const float*)d_in[15], *rm3 = (const float*)d_in[16],
                *rv3 = (const float*)d_in[17];
    const float *w4 = (const float*)d_in[18], *gg4 = (const float*)d_in[19],
                *b4 = (const float*)d_in[20], *rm4 = (const float*)d_in[21],
                *rv4 = (const float*)d_in[22];
    float* out = (float*)d_out;
    const int nv = in_sizes[0] / 3;

    float *h1, *h2, *h3;
    unsigned char *m1, *m2, *m3;
    cudaGetSymbolAddress((void**)&h1, g_h1);
    cudaGetSymbolAddress((void**)&m1, g_m1);
    cudaGetSymbolAddress((void**)&h2, g_h2);
    cudaGetSymbolAddress((void**)&m2, g_m2);
    cudaGetSymbolAddress((void**)&h3, g_h3);
    cudaGetSymbolAddress((void**)&m3, g_m3);

    cudaMemsetAsync(h1, 0, (size_t)B_ * 16 * PLANE1 * sizeof(float));
    cudaMemsetAsync(m1, 0, (size_t)B_ * PLANE1 + 16);
    cudaMemsetAsync(h2, 0, (size_t)B_ * 32 * PLANE2 * sizeof(float));
    cudaMemsetAsync(m2, 0, (size_t)B_ * PLANE2 + 16);
    cudaMemsetAsync(h3, 0, (size_t)B_ * 64 * PLANE3 * sizeof(float));

    // block1 sparse
    {
        int nthreads = nv * 16;
        scatter_conv1<<<(nthreads + 255) / 256, 256>>>(vf, coors, h1, m1, w1, nv);
        dim3 grid((unsigned)((PLANE1 / 4 + 255) / 256), B_ * 16);
        bn_pass<16, PLANE1><<<grid, 256>>>(h1, m1, gg1, b1, rm1, rv1);
    }

    dim3 blk(32, 4, 1);   // 128-thread blocks

    // block2: 16->32, (23,258,258)pad -> (11,128,128), out halo (0,1,1)
    // COG=8, TW=4, TH=1, BY=4. grid: y=32, z=4*11*2=88 -> 2816 blocks
    {
        auto k = conv_pad<16, 32, 8, 4, 1, 4, 1, 23, 258, 258, 11, 128, 128,
                          0, 1, 1, 3, 3, 3, 2, 2, 2>;
        size_t smem = (16ull * 27) * 8 * 8;  // 27648
        dim3 grid(1, 32, B_ * 11 * 4);
        k<<<grid, blk, smem>>>(h1, m1, h2, m2, w2, gg2, b2, rm2, rv2);
    }
    // block3: 32->64, (11,130,130)pad -> (5,64,64) raw, CI split x8
    // COG=8, TW=2, TH=2, BY=4. grid: y=8, z=8*5*2*8=640 -> 5120 blocks
    // (4.94 waves at 7 blocks/SM -> ~1% quantization waste vs 38% at x2)
    {
        auto k = conv_pad<32, 64, 8, 2, 2, 4, 8, 11, 130, 130, 5, 64, 64,
                          0, 0, 0, 3, 3, 3, 2, 2, 2>;
        size_t smem = (4ull * 27) * 8 * 8;   // 6912 (CIL=4)
        dim3 grid(1, 8, 8 * 5 * B_ * 8);
        k<<<grid, blk, smem>>>(h2, m2, h3, m3, w3, gg3, b3, rm3, rv3);
        dim3 bgrid((unsigned)((PLANE3 / 4 + 255) / 256), B_ * 64);
        bn_pass<64, PLANE3><<<bgrid, 256>>>(h3, m3, gg3, b3, rm3, rv3);
    }
    // block4: 64->64, k(3,1,1) s(2,1,1), (5,64,64) -> (2,64,64) = d_out
    // COG=8, TW=2, TH=2, BY=4. grid: y=8 covers oh 0..63
    {
        auto k = conv_pad<64, 64, 8, 2, 2, 4, 1, 5, 64, 64, 2, 64, 64,
                          0, 0, 0, 3, 1, 1, 2, 1, 1>;
        size_t smem = (64ull * 3) * 8 * 8;   // 12288
        dim3 grid(1, 8, 8 * 2 * B_);
        k<<<grid, blk, smem>>>(h3, m3, out, m3, w4, gg4, b4, rm4, rv4);
    }
}

// round 14
// speedup vs baseline: 1.1206x; 1.0200x over previous
#include <cuda_runtime.h>
#include <cuda_bf16.h>

// ---------------------------------------------------------------------------
// SpMiddleFHDLite — sparse block1 + padded dense convs, packed fma.rn.f32x2.
// R9 inner loop; R13 conv3 NSPLIT=8; R14: mask pass moved after conv loop,
// bitmask 'any', __launch_bounds__(128,7) for 7 blocks/SM residency.
// ---------------------------------------------------------------------------

#define EPS 1e-3f
typedef unsigned long long u64;

static constexpr int B_ = 2;

static constexpr int PD1 = 23, PH1 = 258, PW1 = 258;   // h1 + halo(1,1,1)
static constexpr long long PLANE1 = (long long)PD1 * PH1 * PW1;
static constexpr int PD2 = 11, PH2 = 130, PW2 = 130;   // h2 + halo(0,1,1)
static constexpr long long PLANE2 = (long long)PD2 * PH2 * PW2;
static constexpr long long PLANE3 = 5LL * 64 * 64;     // h3 (no halo)

__device__ __align__(256) float         g_h1[B_ * 16 * PLANE1];
__device__ __align__(256) unsigned char g_m1[B_ * PLANE1 + 16];
__device__ __align__(256) float         g_h2[B_ * 32 * PLANE2];
__device__ __align__(256) unsigned char g_m2[B_ * PLANE2 + 16];
__device__ __align__(256) float         g_h3[B_ * 64 * PLANE3];
__device__ __align__(256) unsigned char g_m3[B_ * PLANE3 + 16];

// ---------------------------------------------------------------------------
__device__ __forceinline__ u64 pk2(float lo, float hi) {
    u64 r;
    unsigned l = __float_as_uint(lo), h = __float_as_uint(hi);
    asm("mov.b64 %0, {%1,%2};" : "=l"(r) : "r"(l), "r"(h));
    return r;
}
__device__ __forceinline__ void upk2(u64 v, float& lo, float& hi) {
    unsigned l, h;
    asm("mov.b64 {%0,%1}, %2;" : "=r"(l), "=r"(h) : "l"(v));
    lo = __uint_as_float(l); hi = __uint_as_float(h);
}
__device__ __forceinline__ void fma2(u64& d, u64 a, u64 b) {
    asm("fma.rn.f32x2 %0, %1, %2, %0;" : "+l"(d) : "l"(a), "l"(b));
}

// ---------------------------------------------------------------------------
// Sparse block1: each thread = (voxel, co). Scatter w.f into h1 accumulator.
// ---------------------------------------------------------------------------
__global__ void __launch_bounds__(256)
scatter_conv1(const float* __restrict__ vf, const int* __restrict__ coors,
              float* __restrict__ h1, unsigned char* __restrict__ m1,
              const float* __restrict__ W, int nv) {
    __shared__ float sw[16 * 3 * 27];
    int tid = threadIdx.x;
    for (int i = tid; i < 16 * 3 * 27; i += 256) sw[i] = W[i];
    __syncthreads();

    int g = blockIdx.x * 256 + tid;
    int vi = g >> 4, co = g & 15;
    if (vi >= nv) return;

    float f0 = vf[3 * vi], f1 = vf[3 * vi + 1], f2 = vf[3 * vi + 2];
    int4 cz = *reinterpret_cast<const int4*>(coors + 4 * vi);
    int b = cz.x, z = cz.y, y = cz.z, x = cz.w;

    int odl[2], kdl[2], nz = 1;
    if (z & 1) { odl[0] = (z - 1) >> 1; kdl[0] = 2; odl[1] = (z + 1) >> 1; kdl[1] = 0;
                 nz = (((z + 1) >> 1) < 21) ? 2 : 1; }
    else       { odl[0] = z >> 1; kdl[0] = 1; }
    int ohl[2], khl[2], ny = 1;
    if (y & 1) { ohl[0] = (y - 1) >> 1; khl[0] = 2; ohl[1] = (y + 1) >> 1; khl[1] = 0;
                 ny = (((y + 1) >> 1) < 256) ? 2 : 1; }
    else       { ohl[0] = y >> 1; khl[0] = 1; }
    int owl[2], kwl[2], nx = 1;
    if (x & 1) { owl[0] = (x - 1) >> 1; kwl[0] = 2; owl[1] = (x + 1) >> 1; kwl[1] = 0;
                 nx = (((x + 1) >> 1) < 256) ? 2 : 1; }
    else       { owl[0] = x >> 1; kwl[0] = 1; }

    const float* wc = &sw[co * 81];
    float* hc = h1 + (size_t)(b * 16 + co) * PLANE1;
    unsigned char* mb = m1 + (size_t)b * PLANE1;

    for (int iz = 0; iz < nz; iz++)
        for (int iy = 0; iy < ny; iy++)
            for (int ix = 0; ix < nx; ix++) {
                int k = (kdl[iz] * 3 + khl[iy]) * 3 + kwl[ix];
                float val = wc[k] * f0 + wc[27 + k] * f1 + wc[54 + k] * f2;
                size_t sp = (size_t)(odl[iz] + 1) * (PH1 * PW1)
                          + (size_t)(ohl[iy] + 1) * PW1 + (owl[ix] + 1);
                atomicAdd(hc + sp, val);
                if (co == 0) mb[sp] = 1;
            }
}

// ---------------------------------------------------------------------------
// BN+ReLU+mask elementwise pass, in place.
// ---------------------------------------------------------------------------
template<int CH, long long PLANE>
__global__ void __launch_bounds__(256)
bn_pass(float* __restrict__ h, const unsigned char* __restrict__ m,
        const float* __restrict__ Ga, const float* __restrict__ Be,
        const float* __restrict__ Rm, const float* __restrict__ Rv) {
    int c = blockIdx.y % CH;
    int b = blockIdx.y / CH;
    float inv = Ga[c] * rsqrtf(Rv[c] + EPS);
    float sh  = Be[c] - Rm[c] * inv;
    size_t p = ((size_t)blockIdx.x * 256 + threadIdx.x) * 4;
    if (p >= (size_t)PLANE) return;
    float4* vp = reinterpret_cast<float4*>(h + (size_t)blockIdx.y * PLANE + p);
    float4 v = *vp;
    uchar4 mm = *reinterpret_cast<const uchar4*>(m + (size_t)b * PLANE + p);
    v.x = mm.x ? fmaxf(fmaf(v.x, inv, sh), 0.f) : 0.f;
    v.y = mm.y ? fmaxf(fmaf(v.y, inv, sh), 0.f) : 0.f;
    v.z = mm.z ? fmaxf(fmaf(v.z, inv, sh), 0.f) : 0.f;
    v.w = mm.w ? fmaxf(fmaf(v.w, inv, sh), 0.f) : 0.f;
    *vp = v;
}

// ---------------------------------------------------------------------------
// Padded dense conv (+ optional fused BN/ReLU/mask), packed f32x2 FMA.
// Thread tile: TW x TH outputs x COG channels (COG even).
// Weights read from smem as ulonglong2 (2 co per LDS.128).
// Mask OR computed AFTER the conv loop (keeps regs low in hot region),
// packed into one bitmask register.
// NSPLIT>1: raw partial sums via atomicAdd (bn applied by later bn_pass).
// KW==3 && SW==2: kw0/kw1 taps share one float2 load.
// ---------------------------------------------------------------------------
template<int CI, int CO, int COG, int TW, int TH, int BY, int NSPLIT,
         int IDP, int IHP, int IWP,
         int OD, int OH, int OW,
         int OPD, int OPH, int OPW,
         int KD, int KH, int KW, int SD, int SH, int SW>
__global__ void __launch_bounds__(32 * BY, 7)
conv_pad(const float* __restrict__ in, const unsigned char* __restrict__ mi,
         float* __restrict__ out, unsigned char* __restrict__ mo,
         const float* __restrict__ Wt, const float* __restrict__ Ga,
         const float* __restrict__ Be, const float* __restrict__ Rm,
         const float* __restrict__ Rv) {
    constexpr int NCOG = CO / COG;
    constexpr int NT = TW * TH;      // even, <= 32
    constexpr int NP = NT / 2;
    constexpr int NTHR = 32 * BY;
    constexpr int CIL = CI / NSPLIT;
    constexpr int WSTEPS = CIL * KD * KH * KW;
    constexpr int ODP = OD + 2 * OPD, OHP = OH + 2 * OPH, OWP = OW + 2 * OPW;
    constexpr bool KW3S2 = (KW == 3 && SW == 2);
    static_assert(COG % 2 == 0, "COG even");
    extern __shared__ u64 sw2[];

    const int tid = threadIdx.y * 32 + threadIdx.x;
    int zi = blockIdx.z;
    const int cg = zi % NCOG; zi /= NCOG;
    const int od = zi % OD;  zi /= OD;
    const int b  = zi % B_;
    const int sp = zi / B_;          // ci split index
    const int ci0 = sp * CIL;

    for (int i = tid; i < WSTEPS * COG; i += NTHR) {
        int co = i % COG; int r = i / COG;
        int kw = r % KW; r /= KW;
        int kh = r % KH; r /= KH;
        int kd = r % KD; int cil = r / KD;
        float w = Wt[((((cg * COG + co) * CI + ci0 + cil) * KD + kd) * KH + kh) * KW + kw];
        sw2[i] = pk2(w, w);
    }
    __syncthreads();

    const int ow0 = threadIdx.x;                           // + 32*tw
    const int oh0 = (blockIdx.y * BY + threadIdx.y) * TH;  // + th

    // ---- accumulation (mask computed after, to keep regs low here) ----
    u64 acc[COG][NP];
#pragma unroll
    for (int co = 0; co < COG; co++)
#pragma unroll
        for (int p = 0; p < NP; p++) acc[co][p] = 0ull;

    const float* inb = in + ((size_t)b * CI + ci0) * IDP * IHP * IWP;
#pragma unroll 1
    for (int cil = 0; cil < CIL; cil++) {
#pragma unroll
        for (int kd = 0; kd < KD; kd++) {
            const float* pl = inb + ((size_t)cil * IDP + od * SD + kd) * (IHP * IWP);
#pragma unroll
            for (int kh = 0; kh < KH; kh++) {
                const float* row[TH];
#pragma unroll
                for (int th = 0; th < TH; th++)
                    row[th] = pl + ((size_t)(oh0 + th) * SH + kh) * IWP;

                if (KW3S2) {
                    float2 a01[NT]; float a2[NT];
#pragma unroll
                    for (int th = 0; th < TH; th++)
#pragma unroll
                        for (int tw = 0; tw < TW; tw++) {
                            int iw = (ow0 + 32 * tw) * 2;
                            a01[th * TW + tw] =
                                *reinterpret_cast<const float2*>(row[th] + iw);
                            a2[th * TW + tw] = row[th][iw + 2];
                        }
#pragma unroll
                    for (int kw = 0; kw < 3; kw++) {
                        u64 vp[NP];
#pragma unroll
                        for (int p = 0; p < NP; p++) {
                            int t0 = 2 * p, t1 = 2 * p + 1;
                            float v0 = (kw == 0) ? a01[t0].x : (kw == 1) ? a01[t0].y : a2[t0];
                            float v1 = (kw == 0) ? a01[t1].x : (kw == 1) ? a01[t1].y : a2[t1];
                            vp[p] = pk2(v0, v1);
                        }
                        const u64* wp = &sw2[(((cil * KD + kd) * KH + kh) * 3 + kw) * COG];
#pragma unroll
                        for (int co2 = 0; co2 < COG / 2; co2++) {
                            ulonglong2 ww =
                                *reinterpret_cast<const ulonglong2*>(wp + 2 * co2);
#pragma unroll
                            for (int p = 0; p < NP; p++) fma2(acc[2 * co2][p], vp[p], ww.x);
#pragma unroll
                            for (int p = 0; p < NP; p++) fma2(acc[2 * co2 + 1][p], vp[p], ww.y);
                        }
                    }
                } else {
#pragma unroll
                    for (int kw = 0; kw < KW; kw++) {
                        u64 vp[NP];
#pragma unroll
                        for (int p = 0; p < NP; p++) {
                            int t0 = 2 * p, t1 = 2 * p + 1;
                            int th0 = t0 / TW, tw0 = t0 % TW;
                            int th1 = t1 / TW, tw1 = t1 % TW;
                            float v0 = row[th0][(ow0 + 32 * tw0) * SW + kw];
                            float v1 = row[th1][(ow0 + 32 * tw1) * SW + kw];
                            vp[p] = pk2(v0, v1);
                        }
                        const u64* wp = &sw2[(((cil * KD + kd) * KH + kh) * KW + kw) * COG];
#pragma unroll
                        for (int co2 = 0; co2 < COG / 2; co2++) {
                            ulonglong2 ww =
                                *reinterpret_cast<const ulonglong2*>(wp + 2 * co2);
#pragma unroll
                            for (int p = 0; p < NP; p++) fma2(acc[2 * co2][p], vp[p], ww.x);
#pragma unroll
                            for (int p = 0; p < NP; p++) fma2(acc[2 * co2 + 1][p], vp[p], ww.y);
                        }
                    }
                }
            }
        }
    }

    // ---- mask pass (bitmask; after conv loop) ----
    unsigned anyb = 0;
    if (NSPLIT == 1 || (cg == 0 && sp == 0)) {
        const unsigned char* mb = mi + (size_t)b * IDP * IHP * IWP;
#pragma unroll
        for (int kd = 0; kd < KD; kd++)
#pragma unroll
            for (int kh = 0; kh < KH; kh++)
#pragma unroll
                for (int th = 0; th < TH; th++) {
                    const unsigned char* mrow =
                        mb + ((size_t)(od * SD + kd) * IHP + (oh0 + th) * SH + kh) * IWP;
#pragma unroll
                    for (int kw = 0; kw < KW; kw++)
#pragma unroll
                        for (int tw = 0; tw < TW; tw++)
                            anyb |= (mrow[(ow0 + 32 * tw) * SW + kw] ? 1u : 0u)
                                    << (th * TW + tw);
                }
    }

    if (NSPLIT > 1) {
#pragma unroll
        for (int co = 0; co < COG; co++) {
            int c = cg * COG + co;
            size_t obc = ((size_t)(b * CO + c) * ODP + od) * ((size_t)OHP * OWP);
#pragma unroll
            for (int p = 0; p < NP; p++) {
                float a0, a1;
                upk2(acc[co][p], a0, a1);
                int t0 = 2 * p, t1 = 2 * p + 1;
                int th0 = t0 / TW, tw0 = t0 % TW;
                int th1 = t1 / TW, tw1 = t1 % TW;
                atomicAdd(&out[obc + (size_t)(oh0 + th0) * OWP + (ow0 + 32 * tw0)], a0);
                atomicAdd(&out[obc + (size_t)(oh0 + th1) * OWP + (ow0 + 32 * tw1)], a1);
            }
        }
        if (cg == 0 && sp == 0) {
            size_t mbc = ((size_t)b * ODP + od) * ((size_t)OHP * OWP);
#pragma unroll
            for (int t = 0; t < NT; t++) {
                int th = t / TW, tw = t % TW;
                mo[mbc + (size_t)(oh0 + th) * OWP + (ow0 + 32 * tw)] =
                    (anyb >> t) & 1u;
            }
        }
    } else {
#pragma unroll
        for (int co = 0; co < COG; co++) {
            int c = cg * COG + co;
            float inv = Ga[c] * rsqrtf(Rv[c] + EPS);
            float sh  = Be[c] - Rm[c] * inv;
            size_t obc = ((size_t)(b * CO + c) * ODP + od + OPD) * ((size_t)OHP * OWP);
#pragma unroll
            for (int p = 0; p < NP; p++) {
                float a0, a1;
                upk2(acc[co][p], a0, a1);
                int t0 = 2 * p, t1 = 2 * p + 1;
                int th0 = t0 / TW, tw0 = t0 % TW;
                int th1 = t1 / TW, tw1 = t1 % TW;
                float v0 = ((anyb >> t0) & 1u) ? fmaxf(fmaf(a0, inv, sh), 0.f) : 0.f;
                float v1 = ((anyb >> t1) & 1u) ? fmaxf(fmaf(a1, inv, sh), 0.f) : 0.f;
                out[obc + (size_t)(oh0 + th0 + OPH) * OWP + (ow0 + 32 * tw0 + OPW)] = v0;
                out[obc + (size_t)(oh0 + th1 + OPH) * OWP + (ow0 + 32 * tw1 + OPW)] = v1;
            }
        }
        if (cg == 0) {
            size_t mbc = ((size_t)b * ODP + od + OPD) * ((size_t)OHP * OWP);
#pragma unroll
            for (int t = 0; t < NT; t++) {
                int th = t / TW, tw = t % TW;
                mo[mbc + (size_t)(oh0 + th + OPH) * OWP + (ow0 + 32 * tw + OPW)] =
                    (anyb >> t) & 1u;
            }
        }
    }
}

// ---------------------------------------------------------------------------
extern "C" void kernel_launch(void* const* d_in, const int* in_sizes, int n_in,
                              void* d_out, int out_size) {
    const float* vf    = (const float*)d_in[0];
    const int*   coors = (const int*)d_in[1];
    const float *w1 = (const float*)d_in[3],  *gg1 = (const float*)d_in[4],
                *b1 = (const float*)d_in[5],  *rm1 = (const float*)d_in[6],
                *rv1 = (const float*)d_in[7];
    const float *w2 = (const float*)d_in[8],  *gg2 = (const float*)d_in[9],
                *b2 = (const float*)d_in[10], *rm2 = (const float*)d_in[11],
                *rv2 = (const float*)d_in[12];
    const float *w3 = (const float*)d_in[13], *gg3 = (const float*)d_in[14],
                *b3 = (const float*)d_in[15], *rm3 = (const float*)d_in[16],
                *rv3 = (const float*)d_in[17];
    const float *w4 = (const float*)d_in[18], *gg4 = (const float*)d_in[19],
                *b4 = (const float*)d_in[20], *rm4 = (const float*)d_in[21],
                *rv4 = (const float*)d_in[22];
    float* out = (float*)d_out;
    const int nv = in_sizes[0] / 3;

    float *h1, *h2, *h3;
    unsigned char *m1, *m2, *m3;
    cudaGetSymbolAddress((void**)&h1, g_h1);
    cudaGetSymbolAddress((void**)&m1, g_m1);
    cudaGetSymbolAddress((void**)&h2, g_h2);
    cudaGetSymbolAddress((void**)&m2, g_m2);
    cudaGetSymbolAddress((void**)&h3, g_h3);
    cudaGetSymbolAddress((void**)&m3, g_m3);

    cudaMemsetAsync(h1, 0, (size_t)B_ * 16 * PLANE1 * sizeof(float));
    cudaMemsetAsync(m1, 0, (size_t)B_ * PLANE1 + 16);
    cudaMemsetAsync(h2, 0, (size_t)B_ * 32 * PLANE2 * sizeof(float));
    cudaMemsetAsync(m2, 0, (size_t)B_ * PLANE2 + 16);
    cudaMemsetAsync(h3, 0, (size_t)B_ * 64 * PLANE3 * sizeof(float));

    // block1 sparse
    {
        int nthreads = nv * 16;
        scatter_conv1<<<(nthreads + 255) / 256, 256>>>(vf, coors, h1, m1, w1, nv);
        dim3 grid((unsigned)((PLANE1 / 4 + 255) / 256), B_ * 16);
        bn_pass<16, PLANE1><<<grid, 256>>>(h1, m1, gg1, b1, rm1, rv1);
    }

    dim3 blk(32, 4, 1);   // 128-thread blocks

    // block2: 16->32, (23,258,258)pad -> (11,128,128), out halo (0,1,1)
    // COG=8, TW=4, TH=1, BY=4. grid: y=32, z=4*11*2=88 -> 2816 blocks
    {
        auto k = conv_pad<16, 32, 8, 4, 1, 4, 1, 23, 258, 258, 11, 128, 128,
                          0, 1, 1, 3, 3, 3, 2, 2, 2>;
        size_t smem = (16ull * 27) * 8 * 8;  // 27648
        dim3 grid(1, 32, B_ * 11 * 4);
        k<<<grid, blk, smem>>>(h1, m1, h2, m2, w2, gg2, b2, rm2, rv2);
    }
    // block3: 32->64, (11,130,130)pad -> (5,64,64) raw, CI split x8
    // COG=8, TW=2, TH=2, BY=4. grid: y=8, z=8*5*2*8=640 -> 5120 blocks
    {
        auto k = conv_pad<32, 64, 8, 2, 2, 4, 8, 11, 130, 130, 5, 64, 64,
                          0, 0, 0, 3, 3, 3, 2, 2, 2>;
        size_t smem = (4ull * 27) * 8 * 8;   // 6912 (CIL=4)
        dim3 grid(1, 8, 8 * 5 * B_ * 8);
        k<<<grid, blk, smem>>>(h2, m2, h3, m3, w3, gg3, b3, rm3, rv3);
        dim3 bgrid((unsigned)((PLANE3 / 4 + 255) / 256), B_ * 64);
        bn_pass<64, PLANE3><<<bgrid, 256>>>(h3, m3, gg3, b3, rm3, rv3);
    }
    // block4: 64->64, k(3,1,1) s(2,1,1), (5,64,64) -> (2,64,64) = d_out
    // COG=8, TW=2, TH=2, BY=4. grid: y=8 covers oh 0..63
    {
        auto k = conv_pad<64, 64, 8, 2, 2, 4, 1, 5, 64, 64, 2, 64, 64,
                          0, 0, 0, 3, 1, 1, 2, 1, 1>;
        size_t smem = (64ull * 3) * 8 * 8;   // 12288
        dim3 grid(1, 8, 8 * 2 * B_);
        k<<<grid, blk, smem>>>(h3, m3, out, m3, w4, gg4, b4, rm4, rv4);
    }
}